// round 7
// baseline (speedup 1.0000x reference)
#include <cuda_runtime.h>
#include <cstdint>
#include <cstdio>

// ---------------- problem constants ----------------
#define BB   2
#define DD   32
#define HH   56
#define WW   56
#define CC   96
#define HEADS 3
#define HD   32
#define NN   98          // window tokens = 2*7*7
#define NWIN 1024        // windows per batch = 16*8*8
#define BW   (BB*NWIN)   // 2048 windows
#define TT   (BW*NN)     // 200704 tokens
#define HID  384

// ---------------- scratch (device globals; allocation-free) ----------------
__device__ float g_xw  [(size_t)TT*CC];
__device__ float g_qkv [(size_t)TT*3*CC];
__device__ float g_ao  [(size_t)TT*CC];
__device__ float g_x1  [(size_t)TT*CC];
__device__ float g_h2  [(size_t)TT*CC];
__device__ float g_hid [(size_t)TT*HID];

// Map window-token index -> spatial token index.
__device__ __forceinline__ int win_to_spatial(int t) {
    int win = t / NN, n = t - win * NN;
    int b  = win >> 10;
    int wi = win & 1023;
    int d0 = wi >> 6, h0 = (wi >> 3) & 7, w0 = wi & 7;
    int dd = n / 49;  int r = n - dd * 49;
    int hh = r / 7;   int ww = r - hh * 7;
    int d = d0 * 2 + dd + 1; if (d >= DD) d -= DD;
    int h = h0 * 7 + hh + 3; if (h >= HH) h -= HH;
    int w = w0 * 7 + ww + 3; if (w >= WW) w -= WW;
    return ((b * DD + d) * HH + h) * WW + w;
}

// ---------------- LayerNorm (warp per token, C=96=3*32) ----------------
__global__ void ln_kernel(const float* __restrict__ in,
                          const float* __restrict__ g,
                          const float* __restrict__ bta,
                          float* __restrict__ out, int gather) {
    int t = blockIdx.x * 4 + (threadIdx.x >> 5);
    int lane = threadIdx.x & 31;
    size_t src = gather ? (size_t)win_to_spatial(t) * CC : (size_t)t * CC;
    float x0 = in[src + lane];
    float x1 = in[src + lane + 32];
    float x2 = in[src + lane + 64];
    float s  = x0 + x1 + x2;
    float sq = x0 * x0 + x1 * x1 + x2 * x2;
    #pragma unroll
    for (int o = 16; o; o >>= 1) {
        s  += __shfl_xor_sync(0xffffffffu, s,  o);
        sq += __shfl_xor_sync(0xffffffffu, sq, o);
    }
    float mean = s * (1.0f / 96.0f);
    float var  = sq * (1.0f / 96.0f) - mean * mean;
    float rst  = rsqrtf(var + 1e-5f);
    size_t dst = (size_t)t * CC;
    out[dst + lane]      = (x0 - mean) * rst * g[lane]      + bta[lane];
    out[dst + lane + 32] = (x1 - mean) * rst * g[lane + 32] + bta[lane + 32];
    out[dst + lane + 64] = (x2 - mean) * rst * g[lane + 64] + bta[lane + 64];
}

// ---------------- tf32 tensor-core GEMM: C[M,Nd] = A[M,K] * W[Nd,K]^T + bias ----
// BM=128, BN=64, BK=32; 256 threads = 8 warps (4 m x 2 n), warp tile 32x32.
// smem holds PRE-CONVERTED tf32 bits, k-pair interleaved within each k8 group
// (k' = 2*(k&3) + ((k>>2)&1)) so each mma fragment pair is one LDS.64.
// SSTR=40 pad -> conflict-free LDS.64 fragment loads.
// EPI: 0 plain; 1 window-scatter + residual; 2 exact GELU; 3 residual add.

#define GBM 128
#define GBN 64
#define GBK 32
#define SSTR 40   // BK + 8

__device__ __forceinline__ uint32_t cvt_tf32(float x) {
    uint32_t r;
    asm("cvt.rna.tf32.f32 %0, %1;" : "=r"(r) : "f"(x));
    return r;
}

__device__ __forceinline__ void mma_tf32(float* d, const uint32_t* a, const uint32_t* b) {
    asm volatile(
        "mma.sync.aligned.m16n8k8.row.col.f32.tf32.tf32.f32 "
        "{%0,%1,%2,%3}, {%4,%5,%6,%7}, {%8,%9}, {%0,%1,%2,%3};\n"
        : "+f"(d[0]), "+f"(d[1]), "+f"(d[2]), "+f"(d[3])
        : "r"(a[0]), "r"(a[1]), "r"(a[2]), "r"(a[3]),
          "r"(b[0]), "r"(b[1]));
}

// store one 8-k group (lo = k0..3, hi = k4..7) into interleaved smem
__device__ __forceinline__ void stage_group(uint32_t* dst, float4 lo, float4 hi) {
    *(uint2*)(dst + 0) = make_uint2(cvt_tf32(lo.x), cvt_tf32(hi.x));
    *(uint2*)(dst + 2) = make_uint2(cvt_tf32(lo.y), cvt_tf32(hi.y));
    *(uint2*)(dst + 4) = make_uint2(cvt_tf32(lo.z), cvt_tf32(hi.z));
    *(uint2*)(dst + 6) = make_uint2(cvt_tf32(lo.w), cvt_tf32(hi.w));
}

template<int EPI>
__global__ void __launch_bounds__(256)
gemm_kernel(const float* __restrict__ A, const float* __restrict__ Wt,
            const float* __restrict__ bias, float* __restrict__ Cout,
            const float* __restrict__ res, int M, int Nd, int K) {
    __shared__ uint32_t As[GBM * SSTR];   // 20480 B
    __shared__ uint32_t Bs[GBN * SSTR];   // 10240 B

    int tid  = threadIdx.x;
    int lane = tid & 31, warp = tid >> 5;
    int wm = warp >> 1;          // 0..3  (32-row slice)
    int wn = warp & 1;           // 0..1  (32-col slice)
    int mBase = blockIdx.y * GBM;
    int nBase = blockIdx.x * GBN;

    // staging assignment: A: row ar (0..127), 16 k-values at ak; B: row br, 8 k at bk
    int ar = tid >> 1,  ak = (tid & 1) * 16;
    int br = tid >> 2,  bk = (tid & 3) * 8;

    float acc[2][4][4];
    #pragma unroll
    for (int mt = 0; mt < 2; mt++)
        #pragma unroll
        for (int nt = 0; nt < 4; nt++)
            #pragma unroll
            for (int e = 0; e < 4; e++) acc[mt][nt][e] = 0.0f;

    const float* Ap = A + (size_t)(mBase + ar) * K + ak;
    const bool  bok = (nBase + br) < Nd;
    const float* Bp = Wt + (size_t)(nBase + br) * K + bk;
    const float4 f4z = make_float4(0.f, 0.f, 0.f, 0.f);

    float4 ra[4], rb[2];
    // prefetch first tile
    #pragma unroll
    for (int p = 0; p < 4; p++) ra[p] = *(const float4*)(Ap + p * 4);
    rb[0] = bok ? *(const float4*)(Bp + 0) : f4z;
    rb[1] = bok ? *(const float4*)(Bp + 4) : f4z;

    int g = lane >> 2, l4 = lane & 3;

    for (int kb = 0; kb < K; kb += GBK) {
        // stage registers -> interleaved tf32 smem
        stage_group(&As[ar * SSTR + ak + 0], ra[0], ra[1]);
        stage_group(&As[ar * SSTR + ak + 8], ra[2], ra[3]);
        stage_group(&Bs[br * SSTR + bk],     rb[0], rb[1]);
        __syncthreads();

        // prefetch next tile while mma runs
        if (kb + GBK < K) {
            #pragma unroll
            for (int p = 0; p < 4; p++)
                ra[p] = *(const float4*)(Ap + kb + GBK + p * 4);
            rb[0] = bok ? *(const float4*)(Bp + kb + GBK + 0) : f4z;
            rb[1] = bok ? *(const float4*)(Bp + kb + GBK + 4) : f4z;
        }

        #pragma unroll
        for (int kk = 0; kk < GBK; kk += 8) {
            uint32_t af[2][4], bf[4][2];
            #pragma unroll
            for (int mt = 0; mt < 2; mt++) {
                int r = wm * 32 + mt * 16 + g;
                uint2 lo = *(const uint2*)&As[r * SSTR + kk + 2 * l4];
                uint2 hi = *(const uint2*)&As[(r + 8) * SSTR + kk + 2 * l4];
                af[mt][0] = lo.x; af[mt][1] = hi.x;
                af[mt][2] = lo.y; af[mt][3] = hi.y;
            }
            #pragma unroll
            for (int nt = 0; nt < 4; nt++) {
                int c = wn * 32 + nt * 8 + g;
                uint2 bb = *(const uint2*)&Bs[c * SSTR + kk + 2 * l4];
                bf[nt][0] = bb.x; bf[nt][1] = bb.y;
            }
            #pragma unroll
            for (int mt = 0; mt < 2; mt++)
                #pragma unroll
                for (int nt = 0; nt < 4; nt++)
                    mma_tf32(acc[mt][nt], af[mt], bf[nt]);
        }
        __syncthreads();
    }

    // epilogue
    #pragma unroll
    for (int mt = 0; mt < 2; mt++) {
        #pragma unroll
        for (int h = 0; h < 2; h++) {
            int m = mBase + wm * 32 + mt * 16 + g + h * 8;
            size_t dstrow;
            if (EPI == 1) dstrow = (size_t)win_to_spatial(m) * Nd;
            else          dstrow = (size_t)m * Nd;
            #pragma unroll
            for (int nt = 0; nt < 4; nt++) {
                #pragma unroll
                for (int e = 0; e < 2; e++) {
                    int n = nBase + wn * 32 + nt * 8 + 2 * l4 + e;
                    if (n < Nd) {
                        float v = acc[mt][nt][h * 2 + e] + bias[n];
                        if (EPI == 0) {
                            Cout[dstrow + n] = v;
                        } else if (EPI == 1) {
                            Cout[dstrow + n] = res[dstrow + n] + v;
                        } else if (EPI == 2) {
                            Cout[dstrow + n] = 0.5f * v * (1.0f + erff(v * 0.70710678118654752f));
                        } else {
                            Cout[dstrow + n] = res[dstrow + n] + v;
                        }
                    }
                }
            }
        }
    }
}

// ---------------- windowed attention: one block per (window, head) ----------------
#define ATTN_SMEM ((3 * 98 * 33 + 98 * 99) * 4)

__global__ void __launch_bounds__(256)
attn_kernel(const float* __restrict__ qkv, const float* __restrict__ mask,
            float* __restrict__ out) {
    int blk  = blockIdx.x;
    int win  = blk / HEADS;
    int head = blk - win * HEADS;
    int wi   = win & 1023;
    extern __shared__ float sm[];
    float* q = sm;                 // 98*33
    float* k = sm + 3234;
    float* v = sm + 6468;
    float* S = sm + 9702;          // 98*99
    int tid = threadIdx.x;
    const float scale = 0.17677669529663687f;

    for (int e = tid; e < NN * HD; e += 256) {
        int i = e >> 5, d = e & 31;
        const float* p = qkv + (size_t)(win * NN + i) * (3 * CC) + head * HD + d;
        q[i * 33 + d] = p[0] * scale;
        k[i * 33 + d] = p[CC];
        v[i * 33 + d] = p[2 * CC];
    }
    __syncthreads();

    const float* mk = mask + (size_t)wi * (NN * NN);
    for (int e = tid; e < 49 * 49; e += 256) {
        int i0 = (e / 49) * 2, j0 = (e % 49) * 2;
        float s00 = 0, s01 = 0, s10 = 0, s11 = 0;
        #pragma unroll
        for (int d = 0; d < HD; d++) {
            float a0 = q[i0 * 33 + d],       a1 = q[(i0 + 1) * 33 + d];
            float b0 = k[j0 * 33 + d],       b1 = k[(j0 + 1) * 33 + d];
            s00 = fmaf(a0, b0, s00); s01 = fmaf(a0, b1, s01);
            s10 = fmaf(a1, b0, s10); s11 = fmaf(a1, b1, s11);
        }
        S[i0 * 99 + j0]           = s00 + mk[i0 * NN + j0];
        S[i0 * 99 + j0 + 1]       = s01 + mk[i0 * NN + j0 + 1];
        S[(i0 + 1) * 99 + j0]     = s10 + mk[(i0 + 1) * NN + j0];
        S[(i0 + 1) * 99 + j0 + 1] = s11 + mk[(i0 + 1) * NN + j0 + 1];
    }
    __syncthreads();

    int warp = tid >> 5, lane = tid & 31;
    for (int i = warp; i < NN; i += 8) {
        float mx = -1e30f;
        for (int j = lane; j < NN; j += 32) mx = fmaxf(mx, S[i * 99 + j]);
        #pragma unroll
        for (int o = 16; o; o >>= 1) mx = fmaxf(mx, __shfl_xor_sync(0xffffffffu, mx, o));
        float sum = 0.0f;
        for (int j = lane; j < NN; j += 32) {
            float ev = __expf(S[i * 99 + j] - mx);
            S[i * 99 + j] = ev;
            sum += ev;
        }
        #pragma unroll
        for (int o = 16; o; o >>= 1) sum += __shfl_xor_sync(0xffffffffu, sum, o);
        float inv = 1.0f / sum;
        for (int j = lane; j < NN; j += 32) S[i * 99 + j] *= inv;
    }
    __syncthreads();

    for (int e = tid; e < 49 * 16; e += 256) {
        int i0 = (e / 16) * 2, d0 = (e & 15) * 2;
        float o00 = 0, o01 = 0, o10 = 0, o11 = 0;
        for (int j = 0; j < NN; j++) {
            float s0 = S[i0 * 99 + j], s1 = S[(i0 + 1) * 99 + j];
            float v0 = v[j * 33 + d0], v1 = v[j * 33 + d0 + 1];
            o00 = fmaf(s0, v0, o00); o01 = fmaf(s0, v1, o01);
            o10 = fmaf(s1, v0, o10); o11 = fmaf(s1, v1, o11);
        }
        size_t ob = (size_t)(win * NN) * CC + head * HD;
        out[ob + (size_t)i0 * CC + d0]           = o00;
        out[ob + (size_t)i0 * CC + d0 + 1]       = o01;
        out[ob + (size_t)(i0 + 1) * CC + d0]     = o10;
        out[ob + (size_t)(i0 + 1) * CC + d0 + 1] = o11;
    }
}

// ---------------- launch ----------------
extern "C" void kernel_launch(void* const* d_in, const int* in_sizes, int n_in,
                              void* d_out, int out_size) {
    const float* x      = (const float*)d_in[0];
    const float* mask   = (const float*)d_in[1];
    const float* n1g    = (const float*)d_in[2];
    const float* n1b    = (const float*)d_in[3];
    const float* qkv_w  = (const float*)d_in[4];
    const float* qkv_b  = (const float*)d_in[5];
    const float* proj_w = (const float*)d_in[6];
    const float* proj_b = (const float*)d_in[7];
    const float* n2g    = (const float*)d_in[8];
    const float* n2b    = (const float*)d_in[9];
    const float* fc1_w  = (const float*)d_in[10];
    const float* fc1_b  = (const float*)d_in[11];
    const float* fc2_w  = (const float*)d_in[12];
    const float* fc2_b  = (const float*)d_in[13];
    float* out = (float*)d_out;

    float *xw, *qkvb, *ao, *x1, *h2, *hid;
    cudaGetSymbolAddress((void**)&xw,   g_xw);
    cudaGetSymbolAddress((void**)&qkvb, g_qkv);
    cudaGetSymbolAddress((void**)&ao,   g_ao);
    cudaGetSymbolAddress((void**)&x1,   g_x1);
    cudaGetSymbolAddress((void**)&h2,   g_h2);
    cudaGetSymbolAddress((void**)&hid,  g_hid);

    cudaFuncSetAttribute(attn_kernel, cudaFuncAttributeMaxDynamicSharedMemorySize,
                         ATTN_SMEM);

    const int mtiles = TT / GBM;   // 1568

    // 1) LN1 + shift + window partition
    ln_kernel<<<TT / 4, 128>>>(x, n1g, n1b, xw, 1);
    // 2) qkv = xw @ qkv_w^T + qkv_b   (N=288)
    gemm_kernel<0><<<dim3(5, mtiles), 256>>>(xw, qkv_w, qkv_b, qkvb, nullptr,
                                             TT, 3 * CC, CC);
    // 3) windowed attention (+mask, softmax)
    attn_kernel<<<BW * HEADS, 256, ATTN_SMEM>>>(qkvb, mask, ao);
    // 4) proj + window reverse + unshift + residual(x) -> x1
    gemm_kernel<1><<<dim3(2, mtiles), 256>>>(ao, proj_w, proj_b, x1, x,
                                             TT, CC, CC);
    // 5) LN2
    ln_kernel<<<TT / 4, 128>>>(x1, n2g, n2b, h2, 0);
    // 6) fc1 + exact GELU
    gemm_kernel<2><<<dim3(6, mtiles), 256>>>(h2, fc1_w, fc1_b, hid, nullptr,
                                             TT, HID, CC);
    // 7) fc2 + residual(x1) -> out
    gemm_kernel<3><<<dim3(2, mtiles), 256>>>(hid, fc2_w, fc2_b, out, x1,
                                             TT, CC, HID);
}

// round 8
// speedup vs baseline: 1.1601x; 1.1601x over previous
#include <cuda_runtime.h>
#include <cstdint>
#include <cstdio>

// ---------------- problem constants ----------------
#define BB   2
#define DD   32
#define HH   56
#define WW   56
#define CC   96
#define HEADS 3
#define HD   32
#define NN   98          // window tokens = 2*7*7
#define NWIN 1024        // windows per batch = 16*8*8
#define BW   (BB*NWIN)   // 2048 windows
#define TT   (BW*NN)     // 200704 tokens
#define HID  384

// ---------------- scratch (device globals; allocation-free) ----------------
__device__ float g_xw  [(size_t)TT*CC];     // LN1 out (tf32-rounded)
__device__ float g_qkv [(size_t)TT*3*CC];
__device__ float g_ao  [(size_t)TT*CC];     // attn out (tf32-rounded)
__device__ float g_x1  [(size_t)TT*CC];
__device__ float g_h2  [(size_t)TT*CC];     // LN2 out (tf32-rounded)
__device__ float g_hid [(size_t)TT*HID];    // gelu out (tf32-rounded)

// rounded weights: qkv | proj | fc1 | fc2
#define WQKV_OFF 0
#define WPROJ_OFF 27648
#define WFC1_OFF 36864
#define WFC2_OFF 73728
#define WTOT     110592
__device__ float g_wr[WTOT];

__device__ __forceinline__ uint32_t cvt_tf32(float x) {
    uint32_t r;
    asm("cvt.rna.tf32.f32 %0, %1;" : "=r"(r) : "f"(x));
    return r;
}
__device__ __forceinline__ float round_tf32(float x) {
    return __uint_as_float(cvt_tf32(x));
}

// Map window-token index -> spatial token index.
__device__ __forceinline__ int win_to_spatial(int t) {
    int win = t / NN, n = t - win * NN;
    int b  = win >> 10;
    int wi = win & 1023;
    int d0 = wi >> 6, h0 = (wi >> 3) & 7, w0 = wi & 7;
    int dd = n / 49;  int r = n - dd * 49;
    int hh = r / 7;   int ww = r - hh * 7;
    int d = d0 * 2 + dd + 1; if (d >= DD) d -= DD;
    int h = h0 * 7 + hh + 3; if (h >= HH) h -= HH;
    int w = w0 * 7 + ww + 3; if (w >= WW) w -= WW;
    return ((b * DD + d) * HH + h) * WW + w;
}

// ---------------- weight rounding (one-shot, tiny) ----------------
__global__ void round_weights_kernel(const float* __restrict__ qkv_w,
                                     const float* __restrict__ proj_w,
                                     const float* __restrict__ fc1_w,
                                     const float* __restrict__ fc2_w,
                                     float* __restrict__ wr) {
    int i = blockIdx.x * 256 + threadIdx.x;
    if (i < WTOT) {
        float v;
        if      (i < WPROJ_OFF) v = qkv_w[i - WQKV_OFF];
        else if (i < WFC1_OFF)  v = proj_w[i - WPROJ_OFF];
        else if (i < WFC2_OFF)  v = fc1_w[i - WFC1_OFF];
        else                    v = fc2_w[i - WFC2_OFF];
        wr[i] = round_tf32(v);
    }
}

// ---------------- LayerNorm (warp per token, C=96=3*32), tf32-rounded out ----
__global__ void ln_kernel(const float* __restrict__ in,
                          const float* __restrict__ g,
                          const float* __restrict__ bta,
                          float* __restrict__ out, int gather) {
    int t = blockIdx.x * 4 + (threadIdx.x >> 5);
    int lane = threadIdx.x & 31;
    size_t src = gather ? (size_t)win_to_spatial(t) * CC : (size_t)t * CC;
    float x0 = in[src + lane];
    float x1 = in[src + lane + 32];
    float x2 = in[src + lane + 64];
    float s  = x0 + x1 + x2;
    float sq = x0 * x0 + x1 * x1 + x2 * x2;
    #pragma unroll
    for (int o = 16; o; o >>= 1) {
        s  += __shfl_xor_sync(0xffffffffu, s,  o);
        sq += __shfl_xor_sync(0xffffffffu, sq, o);
    }
    float mean = s * (1.0f / 96.0f);
    float var  = sq * (1.0f / 96.0f) - mean * mean;
    float rst  = rsqrtf(var + 1e-5f);
    size_t dst = (size_t)t * CC;
    out[dst + lane]      = round_tf32((x0 - mean) * rst * g[lane]      + bta[lane]);
    out[dst + lane + 32] = round_tf32((x1 - mean) * rst * g[lane + 32] + bta[lane + 32]);
    out[dst + lane + 64] = round_tf32((x2 - mean) * rst * g[lane + 64] + bta[lane + 64]);
}

// ---------------- tf32 tensor-core GEMM: C[M,Nd] = A[M,K] * W[Nd,K]^T + bias ----
// BM=128, BN=64, BK=32; 256 threads = 8 warps (4m x 2n), warp tile 32x32.
// Inputs pre-rounded to tf32 -> NO cvt in kernel. cp.async double-buffered.
// smem [row][k], SSTR=36: frag LDS.32 banks (4g+l4) conflict-free;
// cp.async STS.128 at 36*(tid>>3)+4*(tid&7) conflict-free per 8-lane phase.
// EPI: 0 plain; 1 window-scatter + residual; 2 GELU (rounded out); 3 residual.

#define GBM 128
#define GBN 64
#define GBK 32
#define SSTR 36

__device__ __forceinline__ void mma_tf32(float* d, const uint32_t* a, const uint32_t* b) {
    asm volatile(
        "mma.sync.aligned.m16n8k8.row.col.f32.tf32.tf32.f32 "
        "{%0,%1,%2,%3}, {%4,%5,%6,%7}, {%8,%9}, {%0,%1,%2,%3};\n"
        : "+f"(d[0]), "+f"(d[1]), "+f"(d[2]), "+f"(d[3])
        : "r"(a[0]), "r"(a[1]), "r"(a[2]), "r"(a[3]),
          "r"(b[0]), "r"(b[1]));
}

__device__ __forceinline__ void cp16(uint32_t dst_smem, const float* src, bool pred) {
    int sz = pred ? 16 : 0;
    asm volatile("cp.async.ca.shared.global [%0], [%1], 16, %2;\n"
                 :: "r"(dst_smem), "l"(src), "r"(sz));
}

template<int EPI>
__global__ void __launch_bounds__(256)
gemm_kernel(const float* __restrict__ A, const float* __restrict__ Wt,
            const float* __restrict__ bias, float* __restrict__ Cout,
            const float* __restrict__ res, int M, int Nd, int K) {
    __shared__ float As[2][GBM * SSTR];   // 2*18432 B
    __shared__ float Bs[2][GBN * SSTR];   // 2*9216 B

    int tid  = threadIdx.x;
    int lane = tid & 31, warp = tid >> 5;
    int wm = warp >> 1;          // 0..3
    int wn = warp & 1;           // 0..1
    int g  = lane >> 2, l4 = lane & 3;
    int mBase = blockIdx.y * GBM;
    int nBase = blockIdx.x * GBN;

    int lr = tid >> 3;           // 0..31
    int lc = (tid & 7) * 4;      // 0,4,..28

    const float* Ap = A + (size_t)(mBase + lr) * K + lc;
    const float* Bp = Wt + (size_t)(nBase + lr) * K + lc;

    uint32_t asb = (uint32_t)__cvta_generic_to_shared(&As[0][0]);
    uint32_t bsb = (uint32_t)__cvta_generic_to_shared(&Bs[0][0]);

    float acc[2][4][4];
    #pragma unroll
    for (int mt = 0; mt < 2; mt++)
        #pragma unroll
        for (int nt = 0; nt < 4; nt++)
            #pragma unroll
            for (int e = 0; e < 4; e++) acc[mt][nt][e] = 0.0f;

    int nTiles = K / GBK;

    auto prefetch = [&](int s, int kt) {
        uint32_t ad = asb + (uint32_t)(s * GBM * SSTR + lr * SSTR + lc) * 4;
        uint32_t bd = bsb + (uint32_t)(s * GBN * SSTR + lr * SSTR + lc) * 4;
        int kb = kt * GBK;
        #pragma unroll
        for (int i = 0; i < 4; i++)
            cp16(ad + i * 32 * SSTR * 4, Ap + (size_t)i * 32 * K + kb, true);
        #pragma unroll
        for (int i = 0; i < 2; i++)
            cp16(bd + i * 32 * SSTR * 4, Bp + (size_t)i * 32 * K + kb,
                 (nBase + lr + i * 32) < Nd);
        asm volatile("cp.async.commit_group;\n" ::);
    };

    prefetch(0, 0);
    prefetch(1, 1);

    for (int kt = 0; kt < nTiles; kt++) {
        if (kt + 1 < nTiles)
            asm volatile("cp.async.wait_group 1;\n" ::);
        else
            asm volatile("cp.async.wait_group 0;\n" ::);
        __syncthreads();

        int s = kt & 1;
        const float* as = As[s];
        const float* bs = Bs[s];

        #pragma unroll
        for (int kk = 0; kk < GBK; kk += 8) {
            int kq = kk + l4;
            uint32_t af[2][4], bf[4][2];
            #pragma unroll
            for (int mt = 0; mt < 2; mt++) {
                int r = wm * 32 + mt * 16 + g;
                af[mt][0] = __float_as_uint(as[r * SSTR + kq]);
                af[mt][1] = __float_as_uint(as[(r + 8) * SSTR + kq]);
                af[mt][2] = __float_as_uint(as[r * SSTR + kq + 4]);
                af[mt][3] = __float_as_uint(as[(r + 8) * SSTR + kq + 4]);
            }
            #pragma unroll
            for (int nt = 0; nt < 4; nt++) {
                int c = wn * 32 + nt * 8 + g;
                bf[nt][0] = __float_as_uint(bs[c * SSTR + kq]);
                bf[nt][1] = __float_as_uint(bs[c * SSTR + kq + 4]);
            }
            #pragma unroll
            for (int mt = 0; mt < 2; mt++)
                #pragma unroll
                for (int nt = 0; nt < 4; nt++)
                    mma_tf32(acc[mt][nt], af[mt], bf[nt]);
        }
        __syncthreads();
        if (kt + 2 < nTiles) prefetch(s, kt + 2);
    }

    // epilogue
    #pragma unroll
    for (int mt = 0; mt < 2; mt++) {
        #pragma unroll
        for (int h = 0; h < 2; h++) {
            int m = mBase + wm * 32 + mt * 16 + g + h * 8;
            size_t dstrow;
            if (EPI == 1) dstrow = (size_t)win_to_spatial(m) * Nd;
            else          dstrow = (size_t)m * Nd;
            #pragma unroll
            for (int nt = 0; nt < 4; nt++) {
                #pragma unroll
                for (int e = 0; e < 2; e++) {
                    int n = nBase + wn * 32 + nt * 8 + 2 * l4 + e;
                    if (n < Nd) {
                        float v = acc[mt][nt][h * 2 + e] + bias[n];
                        if (EPI == 0) {
                            Cout[dstrow + n] = v;
                        } else if (EPI == 1) {
                            Cout[dstrow + n] = res[dstrow + n] + v;
                        } else if (EPI == 2) {
                            float gl = 0.5f * v * (1.0f + erff(v * 0.70710678118654752f));
                            Cout[dstrow + n] = round_tf32(gl);
                        } else {
                            Cout[dstrow + n] = res[dstrow + n] + v;
                        }
                    }
                }
            }
        }
    }
}

// ---------------- windowed attention: one block per (window, head) ----------------
#define ATTN_SMEM ((3 * 98 * 33 + 98 * 99) * 4)

__global__ void __launch_bounds__(256)
attn_kernel(const float* __restrict__ qkv, const float* __restrict__ mask,
            float* __restrict__ out) {
    int blk  = blockIdx.x;
    int win  = blk / HEADS;
    int head = blk - win * HEADS;
    int wi   = win & 1023;
    extern __shared__ float sm[];
    float* q = sm;                 // 98*33
    float* k = sm + 3234;
    float* v = sm + 6468;
    float* S = sm + 9702;          // 98*99
    int tid = threadIdx.x;
    const float scale = 0.17677669529663687f;

    for (int e = tid; e < NN * HD; e += 256) {
        int i = e >> 5, d = e & 31;
        const float* p = qkv + (size_t)(win * NN + i) * (3 * CC) + head * HD + d;
        q[i * 33 + d] = p[0] * scale;
        k[i * 33 + d] = p[CC];
        v[i * 33 + d] = p[2 * CC];
    }
    __syncthreads();

    const float* mk = mask + (size_t)wi * (NN * NN);
    for (int e = tid; e < 49 * 49; e += 256) {
        int i0 = (e / 49) * 2, j0 = (e % 49) * 2;
        float s00 = 0, s01 = 0, s10 = 0, s11 = 0;
        #pragma unroll
        for (int d = 0; d < HD; d++) {
            float a0 = q[i0 * 33 + d],       a1 = q[(i0 + 1) * 33 + d];
            float b0 = k[j0 * 33 + d],       b1 = k[(j0 + 1) * 33 + d];
            s00 = fmaf(a0, b0, s00); s01 = fmaf(a0, b1, s01);
            s10 = fmaf(a1, b0, s10); s11 = fmaf(a1, b1, s11);
        }
        S[i0 * 99 + j0]           = s00 + mk[i0 * NN + j0];
        S[i0 * 99 + j0 + 1]       = s01 + mk[i0 * NN + j0 + 1];
        S[(i0 + 1) * 99 + j0]     = s10 + mk[(i0 + 1) * NN + j0];
        S[(i0 + 1) * 99 + j0 + 1] = s11 + mk[(i0 + 1) * NN + j0 + 1];
    }
    __syncthreads();

    int warp = tid >> 5, lane = tid & 31;
    for (int i = warp; i < NN; i += 8) {
        float mx = -1e30f;
        for (int j = lane; j < NN; j += 32) mx = fmaxf(mx, S[i * 99 + j]);
        #pragma unroll
        for (int o = 16; o; o >>= 1) mx = fmaxf(mx, __shfl_xor_sync(0xffffffffu, mx, o));
        float sum = 0.0f;
        for (int j = lane; j < NN; j += 32) {
            float ev = __expf(S[i * 99 + j] - mx);
            S[i * 99 + j] = ev;
            sum += ev;
        }
        #pragma unroll
        for (int o = 16; o; o >>= 1) sum += __shfl_xor_sync(0xffffffffu, sum, o);
        float inv = 1.0f / sum;
        for (int j = lane; j < NN; j += 32) S[i * 99 + j] *= inv;
    }
    __syncthreads();

    for (int e = tid; e < 49 * 16; e += 256) {
        int i0 = (e / 16) * 2, d0 = (e & 15) * 2;
        float o00 = 0, o01 = 0, o10 = 0, o11 = 0;
        for (int j = 0; j < NN; j++) {
            float s0 = S[i0 * 99 + j], s1 = S[(i0 + 1) * 99 + j];
            float v0 = v[j * 33 + d0], v1 = v[j * 33 + d0 + 1];
            o00 = fmaf(s0, v0, o00); o01 = fmaf(s0, v1, o01);
            o10 = fmaf(s1, v0, o10); o11 = fmaf(s1, v1, o11);
        }
        size_t ob = (size_t)(win * NN) * CC + head * HD;
        out[ob + (size_t)i0 * CC + d0]           = round_tf32(o00);
        out[ob + (size_t)i0 * CC + d0 + 1]       = round_tf32(o01);
        out[ob + (size_t)(i0 + 1) * CC + d0]     = round_tf32(o10);
        out[ob + (size_t)(i0 + 1) * CC + d0 + 1] = round_tf32(o11);
    }
}

// ---------------- launch ----------------
extern "C" void kernel_launch(void* const* d_in, const int* in_sizes, int n_in,
                              void* d_out, int out_size) {
    const float* x      = (const float*)d_in[0];
    const float* mask   = (const float*)d_in[1];
    const float* n1g    = (const float*)d_in[2];
    const float* n1b    = (const float*)d_in[3];
    const float* qkv_w  = (const float*)d_in[4];
    const float* qkv_b  = (const float*)d_in[5];
    const float* proj_w = (const float*)d_in[6];
    const float* proj_b = (const float*)d_in[7];
    const float* n2g    = (const float*)d_in[8];
    const float* n2b    = (const float*)d_in[9];
    const float* fc1_w  = (const float*)d_in[10];
    const float* fc1_b  = (const float*)d_in[11];
    const float* fc2_w  = (const float*)d_in[12];
    const float* fc2_b  = (const float*)d_in[13];
    float* out = (float*)d_out;

    float *xw, *qkvb, *ao, *x1, *h2, *hid, *wr;
    cudaGetSymbolAddress((void**)&xw,   g_xw);
    cudaGetSymbolAddress((void**)&qkvb, g_qkv);
    cudaGetSymbolAddress((void**)&ao,   g_ao);
    cudaGetSymbolAddress((void**)&x1,   g_x1);
    cudaGetSymbolAddress((void**)&h2,   g_h2);
    cudaGetSymbolAddress((void**)&hid,  g_hid);
    cudaGetSymbolAddress((void**)&wr,   g_wr);

    cudaFuncSetAttribute(attn_kernel, cudaFuncAttributeMaxDynamicSharedMemorySize,
                         ATTN_SMEM);

    const int mtiles = TT / GBM;   // 1568

    // 0) round weights to tf32 (tiny)
    round_weights_kernel<<<(WTOT + 255) / 256, 256>>>(qkv_w, proj_w, fc1_w, fc2_w, wr);
    // 1) LN1 + shift + window partition (tf32-rounded out)
    ln_kernel<<<TT / 4, 128>>>(x, n1g, n1b, xw, 1);
    // 2) qkv = xw @ qkv_w^T + qkv_b   (N=288)
    gemm_kernel<0><<<dim3(5, mtiles), 256>>>(xw, wr + WQKV_OFF, qkv_b, qkvb, nullptr,
                                             TT, 3 * CC, CC);
    // 3) windowed attention (+mask, softmax), tf32-rounded out
    attn_kernel<<<BW * HEADS, 256, ATTN_SMEM>>>(qkvb, mask, ao);
    // 4) proj + window reverse + unshift + residual(x) -> x1
    gemm_kernel<1><<<dim3(2, mtiles), 256>>>(ao, wr + WPROJ_OFF, proj_b, x1, x,
                                             TT, CC, CC);
    // 5) LN2 (tf32-rounded out)
    ln_kernel<<<TT / 4, 128>>>(x1, n2g, n2b, h2, 0);
    // 6) fc1 + exact GELU (tf32-rounded out)
    gemm_kernel<2><<<dim3(6, mtiles), 256>>>(h2, wr + WFC1_OFF, fc1_b, hid, nullptr,
                                             TT, HID, CC);
    // 7) fc2 + residual(x1) -> out
    gemm_kernel<3><<<dim3(2, mtiles), 256>>>(hid, wr + WFC2_OFF, fc2_b, out, x1,
                                             TT, CC, HID);
}